// round 16
// baseline (speedup 1.0000x reference)
#include <cuda_runtime.h>
#include <cuda_bf16.h>

// ---------------- problem constants ----------------
namespace {
constexpr int B_  = 32;
constexpr int N_  = 1000;
constexpr int S_  = 200;
constexpr int D_  = 128;
constexpr int H_  = 8;
constexpr int DK_ = 16;
constexpr int FF_ = 512;
constexpr int NL_ = 3;
constexpr int HK_ = H_ * DK_;          // 128
constexpr int U_  = N_ - S_;           // 800
constexpr int L_  = U_ + 2;            // 802
constexpr int M_  = B_ * L_;           // 25664
constexpr int MT_ = ((M_ + 127) / 128); // 201
constexpr int MT64_ = M_ / 64;          // 401
constexpr int MP_ = MT_ * 128;
constexpr int QT_ = 128;
constexpr int KT2_ = 128;               // attention key tile (doubled)
constexpr int QTILES_  = (L_ + QT_ - 1) / QT_;    // 7
constexpr int NKT2_    = (L_ + KT2_ - 1) / KT2_;  // 7
constexpr float LOG2E = 1.44269504088896f;
constexpr float QS_ = 0.25f * LOG2E;
constexpr int SQW_ = NL_ * D_ * HK_;   // 49152
constexpr int SFW_ = NL_ * D_ * FF_;   // 196608
constexpr int WB_TOTAL_ = 4 * SQW_ + 2 * SFW_;  // 589824
constexpr int CVT_BLKS_ = (WB_TOTAL_ + 1023) / 1024;  // 576
constexpr int GATH_BLKS_ = B_ * 7;      // 224
// mlp_k smem layout (unchanged from R14/R15)
constexpr int HTILE_B_ = 64 * 136 * 2;
constexpr int WTILE_B_ = 128 * 136 * 2;
constexpr int SM_AF_  = 0;
constexpr int SM_OB1_ = HTILE_B_;
constexpr int SM_WT_  = 2 * HTILE_B_;
constexpr int SM_LOG_ = 2 * HTILE_B_ + 2 * WTILE_B_;
constexpr int SM_MLP_ = SM_LOG_ + 256;        // 104704
// attn smem layout (dynamic): Ks[2][128][24], Vs[2][128][24], Pp[8][16][68]
constexpr int SM_KS_  = 0;
constexpr int SM_VS_  = 2 * 128 * 24 * 2;     // 12288
constexpr int SM_PP_  = 2 * SM_VS_;           // 24576
constexpr int SM_ATT_ = SM_PP_ + 8 * 16 * 68 * 4;  // 59392
}

// ---------------- device scratch ----------------
__device__ float g_x    [MP_ * D_];
__device__ float g_logits[M_];
__device__ int   g_unsel[B_ * U_];
__device__ __nv_bfloat16 g_xb [MP_ * D_];
__device__ __nv_bfloat16 g_qb [M_ * D_];
__device__ __nv_bfloat16 g_kb [M_ * D_];
__device__ __nv_bfloat16 g_vb [M_ * D_];
__device__ __nv_bfloat16 g_ob [MP_ * D_];
__device__ __nv_bfloat16 g_wb [WB_TOTAL_];

// ---------------- helpers ----------------
__device__ __forceinline__ float ex2(float x) {
    float y;
    asm("ex2.approx.f32 %0, %1;" : "=f"(y) : "f"(x));
    return y;
}

__device__ __forceinline__ unsigned pk(float lo, float hi) {
    unsigned r;
    asm("cvt.rn.bf16x2.f32 %0, %1, %2;" : "=r"(r) : "f"(hi), "f"(lo));
    return r;
}

__device__ __forceinline__ void ldsm4(unsigned& r0, unsigned& r1, unsigned& r2, unsigned& r3,
                                      const void* p) {
    unsigned a = (unsigned)__cvta_generic_to_shared(p);
    asm volatile("ldmatrix.sync.aligned.m8n8.x4.shared.b16 {%0,%1,%2,%3}, [%4];"
                 : "=r"(r0), "=r"(r1), "=r"(r2), "=r"(r3) : "r"(a));
}
__device__ __forceinline__ void ldsm4t(unsigned& r0, unsigned& r1, unsigned& r2, unsigned& r3,
                                       const void* p) {
    unsigned a = (unsigned)__cvta_generic_to_shared(p);
    asm volatile("ldmatrix.sync.aligned.m8n8.x4.trans.shared.b16 {%0,%1,%2,%3}, [%4];"
                 : "=r"(r0), "=r"(r1), "=r"(r2), "=r"(r3) : "r"(a));
}

__device__ __forceinline__ void mma_bf16(float& d0, float& d1, float& d2, float& d3,
                                         unsigned a0, unsigned a1, unsigned a2, unsigned a3,
                                         unsigned b0, unsigned b1) {
    asm volatile(
        "mma.sync.aligned.m16n8k16.row.col.f32.bf16.bf16.f32 "
        "{%0,%1,%2,%3}, {%4,%5,%6,%7}, {%8,%9}, {%0,%1,%2,%3};"
        : "+f"(d0), "+f"(d1), "+f"(d2), "+f"(d3)
        : "r"(a0), "r"(a1), "r"(a2), "r"(a3), "r"(b0), "r"(b1));
}

__device__ __forceinline__ void cp16(void* smem, const void* gmem) {
    unsigned s = (unsigned)__cvta_generic_to_shared(smem);
    asm volatile("cp.async.ca.shared.global [%0], [%1], 16;" :: "r"(s), "l"(gmem));
}
__device__ __forceinline__ void cp_commit() { asm volatile("cp.async.commit_group;"); }
__device__ __forceinline__ void cp_wait0()  { asm volatile("cp.async.wait_group 0;"); }
__device__ __forceinline__ void cp_wait1()  { asm volatile("cp.async.wait_group 1;"); }

// ---------------- 1a) unselected-index compaction ----------------
__global__ void __launch_bounds__(1024) unselect_k(const int* __restrict__ sel,
                                                   int* __restrict__ unsel) {
    __shared__ int keep[1024];
    __shared__ int scan[1024];
    const int b = blockIdx.x, t = threadIdx.x;
    keep[t] = (t < N_) ? 1 : 0;
    __syncthreads();
    if (t < S_) keep[sel[b * S_ + t]] = 0;
    __syncthreads();
    const int k = keep[t];
    scan[t] = k;
    __syncthreads();
    #pragma unroll
    for (int off = 1; off < 1024; off <<= 1) {
        int add = (t >= off) ? scan[t - off] : 0;
        __syncthreads();
        scan[t] += add;
        __syncthreads();
    }
    if (k && t < N_) unsel[b * U_ + scan[t] - 1] = t;
}

// ---------------- 1b) parallel build x0 + weight cvt ----------------
__global__ void __launch_bounds__(1024) build_cvt_k(
    const float* __restrict__ data, const int* __restrict__ sel,
    const int* __restrict__ unsel,
    const float* __restrict__ Wf, const float* __restrict__ bf,
    const float* __restrict__ Wl, const float* __restrict__ bl,
    const float* __restrict__ Wq, const float* __restrict__ Wk,
    const float* __restrict__ Wv, const float* __restrict__ Wo,
    const float* __restrict__ W1, const float* __restrict__ W2,
    __nv_bfloat16* __restrict__ wb,
    float* __restrict__ x, __nv_bfloat16* __restrict__ xb)
{
    const int t = threadIdx.x;
    if (blockIdx.x >= GATH_BLKS_) {
        const int i = (blockIdx.x - GATH_BLKS_) * 1024 + t;
        if (i >= WB_TOTAL_) return;
        float v;
        if      (i <     SQW_)        v = Wq[i];
        else if (i < 2 * SQW_)        v = Wk[i - SQW_];
        else if (i < 3 * SQW_)        v = Wv[i - 2 * SQW_];
        else if (i < 4 * SQW_)        v = Wo[i - 3 * SQW_];
        else if (i < 4 * SQW_ + SFW_) v = W1[i - 4 * SQW_];
        else                          v = W2[i - 4 * SQW_ - SFW_];
        wb[i] = __float2bfloat16(v);
        return;
    }

    const int b = blockIdx.x / 7;
    const int chunk = blockIdx.x % 7;
    const int r0 = chunk * 128;

    #pragma unroll
    for (int it = 0; it < 4; it++) {
        const int idx = t + it * 1024;
        const int row = idx >> 5;
        const int c4 = (idx & 31) * 4;
        const int l = r0 + row;
        if (l >= L_ || l == 0 || l == L_ - 1) continue;
        const int node = unsel[b * U_ + (l - 1)];
        const float4 v = *(const float4*)&data[((size_t)b * N_ + node) * D_ + c4];
        const size_t ro = ((size_t)b * L_ + l) * D_ + c4;
        *(float4*)&x[ro] = v;
        uint2 w; w.x = pk(v.x, v.y); w.y = pk(v.z, v.w);
        *(uint2*)&xb[ro] = w;
    }

    if (chunk == 0 || chunk == 6) {
        __shared__ float vin[128];
        const bool lastr = (chunk == 6);
        const int node = sel[b * S_ + (lastr ? S_ - 1 : 0)];
        if (t < 128) vin[t] = data[((size_t)b * N_ + node) * D_ + t];
        __syncthreads();
        if (t < 128) {
            const float* W  = lastr ? Wl : Wf;
            const float* bb = lastr ? bl : bf;
            float acc = bb[t];
            #pragma unroll 16
            for (int i = 0; i < D_; i++) acc = fmaf(vin[i], W[i * D_ + t], acc);
            const int l = lastr ? (L_ - 1) : 0;
            const size_t ro = ((size_t)b * L_ + l) * D_ + t;
            x[ro] = acc;
            xb[ro] = __float2bfloat16(acc);
        }
    }
}

// ---------------- 2) fused MLP (unchanged from R14/R15) ----------------
__device__ __forceinline__ void phase_compute(
    const __nv_bfloat16 (*__restrict__ Asm)[136],
    const __nv_bfloat16 (*__restrict__ Wtb)[136],
    int arow, int ac8, int kr, int wn, int lane,
    float (&dst)[8][4])
{
    #pragma unroll
    for (int kt = 0; kt < 8; kt++) {
        unsigned aa[4];
        ldsm4(aa[0], aa[1], aa[2], aa[3], &Asm[arow][kt * 16 + ac8]);
        #pragma unroll
        for (int ntp = 0; ntp < 4; ntp++) {
            unsigned b0, b1v, b2v, b3;
            const int nn = wn * 64 + ntp * 16 + ((lane >> 4) & 1) * 8;
            ldsm4t(b0, b1v, b2v, b3, &Wtb[kt * 16 + kr][nn]);
            mma_bf16(dst[2*ntp][0], dst[2*ntp][1], dst[2*ntp][2], dst[2*ntp][3],
                     aa[0], aa[1], aa[2], aa[3], b0, b1v);
            mma_bf16(dst[2*ntp+1][0], dst[2*ntp+1][1], dst[2*ntp+1][2], dst[2*ntp+1][3],
                     aa[0], aa[1], aa[2], aa[3], b2v, b3);
        }
    }
}

__global__ void __launch_bounds__(256, 2) mlp_k(
    const __nv_bfloat16* __restrict__ ob,
    const __nv_bfloat16* __restrict__ Wo, const float* __restrict__ bo,
    const __nv_bfloat16* __restrict__ W1, const float* __restrict__ b1,
    const __nv_bfloat16* __restrict__ W2, const float* __restrict__ b2,
    float* __restrict__ xf, __nv_bfloat16* __restrict__ xb,
    const float* __restrict__ Wfin, const float* __restrict__ bfin,
    float* __restrict__ logits, int Mreal)
{
    extern __shared__ char dyn[];
    __nv_bfloat16 (*Af)[136]      = (__nv_bfloat16(*)[136])(dyn + SM_AF_);
    __nv_bfloat16 (*Ob1)[136]     = (__nv_bfloat16(*)[136])(dyn + SM_OB1_);
    __nv_bfloat16 (*Wt)[128][136] = (__nv_bfloat16(*)[128][136])(dyn + SM_WT_);
    float* slog = (float*)(dyn + SM_LOG_);

    const int bm = blockIdx.x * 64;
    const int tid = threadIdx.x;
    const int warp = tid >> 5, lane = tid & 31;
    const int wm = warp >> 1, wn = warp & 1;
    const int g = lane >> 2, tg = lane & 3;

    auto stage_w = [&](int buf, const __nv_bfloat16* src, int ld, int row0, int col0) {
        #pragma unroll
        for (int i = 0; i < 8; i++) {
            const int idx = tid + i * 256;
            const int r = idx >> 4, c8 = (idx & 15) * 8;
            cp16(&Wt[buf][r][c8], &src[(size_t)(row0 + r) * ld + col0 + c8]);
        }
        cp_commit();
    };

    #pragma unroll
    for (int i = 0; i < 4; i++) {
        const int idx = tid + i * 256;
        cp16(&Af[idx >> 4][(idx & 15) * 8], &ob[(size_t)(bm + (idx >> 4)) * D_ + (idx & 15) * 8]);
    }
    cp_commit();
    stage_w(0, Wo, D_, 0, 0);

    float acc[8][4];
    #pragma unroll
    for (int b = 0; b < 8; b++)
        #pragma unroll
        for (int c = 0; c < 4; c++) acc[b][c] = 0.f;

    const int lr_lo = wm * 16 + g;
    const int lr_hi = lr_lo + 8;
    const int arow = wm * 16 + (lane & 7) + ((lane >> 3) & 1) * 8;
    const int ac8  = ((lane >> 4) & 1) * 8;
    const int kr   = (lane & 7) + ((lane >> 3) & 1) * 8;

    cp_wait0();
    __syncthreads();
    stage_w(1, W1, FF_, 0, 0);
    phase_compute(Af, Wt[0], arow, ac8, kr, wn, lane, acc);
    __syncthreads();
    #pragma unroll
    for (int nt = 0; nt < 8; nt++) {
        const int cn = wn * 64 + nt * 8 + tg * 2;
        const float b0 = bo[cn], b1v = bo[cn + 1];
        const float2 rlo = *(const float2*)&xf[(size_t)(bm + lr_lo) * D_ + cn];
        const float2 rhi = *(const float2*)&xf[(size_t)(bm + lr_hi) * D_ + cn];
        acc[nt][0] += b0 + rlo.x;  acc[nt][1] += b1v + rlo.y;
        acc[nt][2] += b0 + rhi.x;  acc[nt][3] += b1v + rhi.y;
        *(unsigned*)&Ob1[lr_lo][cn] = pk(acc[nt][0], acc[nt][1]);
        *(unsigned*)&Ob1[lr_hi][cn] = pk(acc[nt][2], acc[nt][3]);
    }

    float acch[8][4];
    #pragma unroll 1
    for (int c = 0; c < 4; c++) {
        const int p1 = 1 + 2 * c;
        const int b1f = p1 & 1;
        const int b2f = (p1 + 1) & 1;

        #pragma unroll
        for (int b = 0; b < 8; b++)
            #pragma unroll
            for (int d = 0; d < 4; d++) acch[b][d] = 0.f;

        cp_wait0();
        __syncthreads();
        stage_w(b2f, W2, D_, c * 128, 0);
        phase_compute(Ob1, Wt[b1f], arow, ac8, kr, wn, lane, acch);
        __syncthreads();
        #pragma unroll
        for (int nt = 0; nt < 8; nt++) {
            const int cn = wn * 64 + nt * 8 + tg * 2;
            const float bb0 = b1[c * 128 + cn], bb1 = b1[c * 128 + cn + 1];
            const float v0 = fmaxf(acch[nt][0] + bb0, 0.f);
            const float v1 = fmaxf(acch[nt][1] + bb1, 0.f);
            const float v2 = fmaxf(acch[nt][2] + bb0, 0.f);
            const float v3 = fmaxf(acch[nt][3] + bb1, 0.f);
            *(unsigned*)&Af[lr_lo][cn] = pk(v0, v1);
            *(unsigned*)&Af[lr_hi][cn] = pk(v2, v3);
        }
        cp_wait0();
        __syncthreads();
        if (c + 1 < 4) stage_w(b1f, W1, FF_, 0, (c + 1) * 128);
        phase_compute(Af, Wt[b2f], arow, ac8, kr, wn, lane, acc);
        __syncthreads();
    }

    const bool do_log = (Wfin != nullptr);
    if (do_log && tid < 64) slog[tid] = 0.f;
    if (do_log) __syncthreads();

    float part[2] = {0.f, 0.f};
    #pragma unroll
    for (int nt = 0; nt < 8; nt++) {
        const int cn = wn * 64 + nt * 8 + tg * 2;
        const float b0 = b2[cn], b1v = b2[cn + 1];
        const float v0 = acc[nt][0] + b0, v1 = acc[nt][1] + b1v;
        const float v2 = acc[nt][2] + b0, v3 = acc[nt][3] + b1v;
        *(float2*)&xf[(size_t)(bm + lr_lo) * D_ + cn] = make_float2(v0, v1);
        *(float2*)&xf[(size_t)(bm + lr_hi) * D_ + cn] = make_float2(v2, v3);
        *(unsigned*)&xb[(size_t)(bm + lr_lo) * D_ + cn] = pk(v0, v1);
        *(unsigned*)&xb[(size_t)(bm + lr_hi) * D_ + cn] = pk(v2, v3);
        if (do_log) {
            const float w0 = Wfin[cn], w1 = Wfin[cn + 1];
            part[0] += v0 * w0 + v1 * w1;
            part[1] += v2 * w0 + v3 * w1;
        }
    }
    if (do_log) {
        #pragma unroll
        for (int hh = 0; hh < 2; hh++) {
            part[hh] += __shfl_xor_sync(0xffffffffu, part[hh], 1);
            part[hh] += __shfl_xor_sync(0xffffffffu, part[hh], 2);
        }
        if (tg == 0) {
            atomicAdd(&slog[lr_lo], part[0]);
            atomicAdd(&slog[lr_hi], part[1]);
        }
        __syncthreads();
        if (tid < 64 && bm + tid < Mreal) logits[bm + tid] = slog[tid] + bfin[0];
    }
}

// ---------------- 3) fused QKV GEMM (unchanged) ----------------
struct GemmSmem {
    __nv_bfloat16 As[3][128][24];
    __nv_bfloat16 Bs[3][16][136];
};

__device__ __forceinline__ void gemm_step(
    const GemmSmem& sm, int buf, int wm, int wn, int lane, float acc[2][8][4])
{
    unsigned aa[2][4];
    #pragma unroll
    for (int mt = 0; mt < 2; mt++) {
        const int row = wm * 32 + mt * 16 + (lane & 7) + ((lane >> 3) & 1) * 8;
        const int c8 = ((lane >> 4) & 1) * 8;
        ldsm4(aa[mt][0], aa[mt][1], aa[mt][2], aa[mt][3], &sm.As[buf][row][c8]);
    }
    const int kr = (lane & 7) + ((lane >> 3) & 1) * 8;
    #pragma unroll
    for (int ntp = 0; ntp < 4; ntp++) {
        unsigned b0, b1, b2, b3;
        const int nn = wn * 64 + ntp * 16 + ((lane >> 4) & 1) * 8;
        ldsm4t(b0, b1, b2, b3, &sm.Bs[buf][kr][nn]);
        #pragma unroll
        for (int mt = 0; mt < 2; mt++) {
            mma_bf16(acc[mt][2*ntp][0], acc[mt][2*ntp][1], acc[mt][2*ntp][2], acc[mt][2*ntp][3],
                     aa[mt][0], aa[mt][1], aa[mt][2], aa[mt][3], b0, b1);
            mma_bf16(acc[mt][2*ntp+1][0], acc[mt][2*ntp+1][1], acc[mt][2*ntp+1][2], acc[mt][2*ntp+1][3],
                     aa[mt][0], aa[mt][1], aa[mt][2], aa[mt][3], b2, b3);
        }
    }
}

__global__ void __launch_bounds__(256) gemm_qkv(
    const __nv_bfloat16* __restrict__ A,
    const __nv_bfloat16* __restrict__ Wq, const __nv_bfloat16* __restrict__ Wk,
    const __nv_bfloat16* __restrict__ Wv,
    __nv_bfloat16* __restrict__ Cq, __nv_bfloat16* __restrict__ Ck,
    __nv_bfloat16* __restrict__ Cv, int Mreal)
{
    __shared__ GemmSmem sm;
    const int which = blockIdx.x;
    const __nv_bfloat16* W = (which == 0) ? Wq : (which == 1) ? Wk : Wv;
    __nv_bfloat16* C = (which == 0) ? Cq : (which == 1) ? Ck : Cv;
    const float osc = (which == 0) ? QS_ : 1.f;
    const int bm = blockIdx.y * 128;
    const int tid = threadIdx.x;
    const int warp = tid >> 5, lane = tid & 31;
    const int wm = warp >> 1, wn = warp & 1;
    const int g = lane >> 2, tg = lane & 3;

    const int arow = tid >> 1, ahalf = (tid & 1) * 8;
    const int brow = tid >> 4, bcol = (tid & 15) * 8;

    float acc[2][8][4];
    #pragma unroll
    for (int a = 0; a < 2; a++)
        #pragma unroll
        for (int b = 0; b < 8; b++)
            #pragma unroll
            for (int c = 0; c < 4; c++) acc[a][b][c] = 0.f;

    cp16(&sm.As[0][arow][ahalf], &A[(size_t)(bm + arow) * D_ + ahalf]);
    cp16(&sm.Bs[0][brow][bcol], &W[(size_t)brow * HK_ + bcol]);
    cp_commit();
    cp16(&sm.As[1][arow][ahalf], &A[(size_t)(bm + arow) * D_ + 16 + ahalf]);
    cp16(&sm.Bs[1][brow][bcol], &W[(size_t)(16 + brow) * HK_ + bcol]);
    cp_commit();

    int buf = 0;
    #pragma unroll 1
    for (int kt = 0; kt < 8; kt++) {
        if (kt + 1 < 8) cp_wait1(); else cp_wait0();
        __syncthreads();
        if (kt + 2 < 8) {
            const int k0 = (kt + 2) * 16;
            const int nb = (buf + 2 >= 3) ? buf - 1 : buf + 2;
            cp16(&sm.As[nb][arow][ahalf], &A[(size_t)(bm + arow) * D_ + k0 + ahalf]);
            cp16(&sm.Bs[nb][brow][bcol], &W[(size_t)(k0 + brow) * HK_ + bcol]);
            cp_commit();
        }
        gemm_step(sm, buf, wm, wn, lane, acc);
        buf = (buf + 1 == 3) ? 0 : buf + 1;
    }

    #pragma unroll
    for (int mt = 0; mt < 2; mt++) {
        const int r_lo = bm + wm * 32 + mt * 16 + g;
        const int r_hi = r_lo + 8;
        #pragma unroll
        for (int nt = 0; nt < 8; nt++) {
            const int cn = wn * 64 + nt * 8 + tg * 2;
            const int hh = cn >> 4, dk = cn & 15;
            if (r_lo < Mreal) {
                const int bb = r_lo / L_, ll = r_lo - bb * L_;
                *(unsigned*)&C[(((size_t)bb * H_ + hh) * L_ + ll) * DK_ + dk] =
                    pk(acc[mt][nt][0] * osc, acc[mt][nt][1] * osc);
            }
            if (r_hi < Mreal) {
                const int bb = r_hi / L_, ll = r_hi - bb * L_;
                *(unsigned*)&C[(((size_t)bb * H_ + hh) * L_ + ll) * DK_ + dk] =
                    pk(acc[mt][nt][2] * osc, acc[mt][nt][3] * osc);
            }
        }
    }
}

// ---------------- 4) bf16 flash attention, KT=128 (halved per-tile overhead) ----------------
__global__ void __launch_bounds__(256) attn_bf16(
    const __nv_bfloat16* __restrict__ q, const __nv_bfloat16* __restrict__ k,
    const __nv_bfloat16* __restrict__ v, __nv_bfloat16* __restrict__ o)
{
    extern __shared__ char dyn[];
    __nv_bfloat16 (*Ks)[KT2_][24] = (__nv_bfloat16(*)[KT2_][24])(dyn + SM_KS_);
    __nv_bfloat16 (*Vs)[KT2_][24] = (__nv_bfloat16(*)[KT2_][24])(dyn + SM_VS_);
    unsigned (*Pp)[16][68]        = (unsigned(*)[16][68])(dyn + SM_PP_);

    const int bh = blockIdx.x;
    const int b = bh >> 3, h = bh & 7;
    const int qt = blockIdx.y;
    const int tid = threadIdx.x, lane = tid & 31, warp = tid >> 5;
    const int g = lane >> 2, tg = lane & 3;

    const __nv_bfloat16* qp = q + (size_t)bh * L_ * DK_;
    const __nv_bfloat16* kp = k + (size_t)bh * L_ * DK_;
    const __nv_bfloat16* vp = v + (size_t)bh * L_ * DK_;

    const int r0 = qt * QT_ + warp * 16 + g;
    const int r1 = r0 + 8;
    const int r0c = r0 < L_ ? r0 : L_ - 1;
    const int r1c = r1 < L_ ? r1 : L_ - 1;
    const unsigned qa0 = *(const unsigned*)&qp[(size_t)r0c * DK_ + 2 * tg];
    const unsigned qa1 = *(const unsigned*)&qp[(size_t)r1c * DK_ + 2 * tg];
    const unsigned qa2 = *(const unsigned*)&qp[(size_t)r0c * DK_ + 2 * tg + 8];
    const unsigned qa3 = *(const unsigned*)&qp[(size_t)r1c * DK_ + 2 * tg + 8];

    float m0 = -1e30f, m1 = -1e30f, l0 = 0.f, l1 = 0.f;
    float oc[2][4];
    #pragma unroll
    for (int nt = 0; nt < 2; nt++)
        #pragma unroll
        for (int c = 0; c < 4; c++) oc[nt][c] = 0.f;

    // staging: threads 0-127 stage K rows, 128-255 stage V rows (2x16B per row)
    const int sr = tid & 127;
    const bool isv = tid >= 128;

    auto stage = [&](int buf, int j0) {
        int jc = j0 + sr; if (jc > L_ - 1) jc = L_ - 1;
        const __nv_bfloat16* src = (isv ? vp : kp) + (size_t)jc * DK_;
        if (isv) { cp16(&Vs[buf][sr][0], src); cp16(&Vs[buf][sr][8], src + 8); }
        else     { cp16(&Ks[buf][sr][0], src); cp16(&Ks[buf][sr][8], src + 8); }
    };

    stage(0, 0);
    cp_commit();

    #pragma unroll 1
    for (int ti = 0; ti < NKT2_; ti++) {
        const int buf = ti & 1;
        const int j0 = ti * KT2_;
        cp_wait0();
        __syncthreads();
        if (ti + 1 < NKT2_) { stage(buf ^ 1, j0 + KT2_); cp_commit(); }

        // S = Q.K^T over 128 keys
        float sc[16][4];
        #pragma unroll
        for (int nt = 0; nt < 16; nt++)
            #pragma unroll
            for (int c = 0; c < 4; c++) sc[nt][c] = 0.f;
        #pragma unroll
        for (int ntp = 0; ntp < 8; ntp++) {
            unsigned b0, b1, b2, b3;
            const int jrow = ntp * 16 + (lane & 7) + ((lane >> 4) & 1) * 8;
            const int kcol = ((lane >> 3) & 1) * 8;
            ldsm4(b0, b1, b2, b3, &Ks[buf][jrow][kcol]);
            mma_bf16(sc[2*ntp][0], sc[2*ntp][1], sc[2*ntp][2], sc[2*ntp][3],
                     qa0, qa1, qa2, qa3, b0, b1);
            mma_bf16(sc[2*ntp+1][0], sc[2*ntp+1][1], sc[2*ntp+1][2], sc[2*ntp+1][3],
                     qa0, qa1, qa2, qa3, b2, b3);
        }
        if (j0 + KT2_ > L_) {
            #pragma unroll
            for (int nt = 0; nt < 16; nt++) {
                const int c = j0 + nt * 8 + 2 * tg;
                if (c     >= L_) { sc[nt][0] = -1e30f; sc[nt][2] = -1e30f; }
                if (c + 1 >= L_) { sc[nt][1] = -1e30f; sc[nt][3] = -1e30f; }
            }
        }
        // online max / rescale
        float nm0 = m0, nm1 = m1;
        #pragma unroll
        for (int nt = 0; nt < 16; nt++) {
            nm0 = fmaxf(nm0, fmaxf(sc[nt][0], sc[nt][1]));
            nm1 = fmaxf(nm1, fmaxf(sc[nt][2], sc[nt][3]));
        }
        nm0 = fmaxf(nm0, __shfl_xor_sync(0xffffffffu, nm0, 1));
        nm0 = fmaxf(nm0, __shfl_xor_sync(0xffffffffu, nm0, 2));
        nm1 = fmaxf(nm1, __shfl_xor_sync(0xffffffffu, nm1, 1));
        nm1 = fmaxf(nm1, __shfl_xor_sync(0xffffffffu, nm1, 2));
        const float f0 = ex2(m0 - nm0);
        const float f1 = ex2(m1 - nm1);
        m0 = nm0; m1 = nm1;
        l0 *= f0; l1 *= f1;
        #pragma unroll
        for (int nt = 0; nt < 2; nt++) {
            oc[nt][0] *= f0; oc[nt][1] *= f0;
            oc[nt][2] *= f1; oc[nt][3] *= f1;
        }
        // P = 2^(S-m) -> bf16 pairs in per-warp smem
        float rs0 = 0.f, rs1 = 0.f;
        #pragma unroll
        for (int nt = 0; nt < 16; nt++) {
            const float p0 = ex2(sc[nt][0] - m0);
            const float p1 = ex2(sc[nt][1] - m0);
            const float p2 = ex2(sc[nt][2] - m1);
            const float p3 = ex2(sc[nt][3] - m1);
            rs0 += p0 + p1;
            rs1 += p2 + p3;
            Pp[warp][g    ][nt * 4 + tg] = pk(p0, p1);
            Pp[warp][g + 8][nt * 4 + tg] = pk(p2, p3);
        }
        rs0 += __shfl_xor_sync(0xffffffffu, rs0, 1);
        rs0 += __shfl_xor_sync(0xffffffffu, rs0, 2);
        rs1 += __shfl_xor_sync(0xffffffffu, rs1, 1);
        rs1 += __shfl_xor_sync(0xffffffffu, rs1, 2);
        l0 += rs0; l1 += rs1;
        __syncwarp();
        // O += P.V
        #pragma unroll
        for (int ks = 0; ks < 8; ks++) {
            unsigned a0, a1, a2, a3;
            const unsigned* pa = &Pp[warp][(lane & 7) + ((lane >> 3) & 1) * 8]
                                         [ks * 8 + ((lane >> 4) & 1) * 4];
            ldsm4(a0, a1, a2, a3, pa);
            unsigned v0, v1, v2, v3;
            const int jrow = ks * 16 + (lane & 7) + ((lane >> 3) & 1) * 8;
            const int dkc = ((lane >> 4) & 1) * 8;
            ldsm4t(v0, v1, v2, v3, &Vs[buf][jrow][dkc]);
            mma_bf16(oc[0][0], oc[0][1], oc[0][2], oc[0][3], a0, a1, a2, a3, v0, v1);
            mma_bf16(oc[1][0], oc[1][1], oc[1][2], oc[1][3], a0, a1, a2, a3, v2, v3);
        }
        __syncwarp();
    }

    const float inv0 = 1.f / l0;
    const float inv1 = 1.f / l1;
    #pragma unroll
    for (int nt = 0; nt < 2; nt++) {
        const int dn = h * DK_ + nt * 8 + 2 * tg;
        if (r0 < L_)
            *(unsigned*)&o[((size_t)b * L_ + r0) * HK_ + dn] =
                pk(oc[nt][0] * inv0, oc[nt][1] * inv0);
        if (r1 < L_)
            *(unsigned*)&o[((size_t)b * L_ + r1) * HK_ + dn] =
                pk(oc[nt][2] * inv1, oc[nt][3] * inv1);
    }
}

// ---------------- 5) finalize (unchanged) ----------------
__global__ void __launch_bounds__(1024) finalize_k(
    const float* __restrict__ logits, const float* __restrict__ ab,
    const int* __restrict__ sel, const int* __restrict__ unsel,
    float* __restrict__ out)
{
    __shared__ float red[32];
    const int b = blockIdx.x, t = threadIdx.x;
    const int lane = t & 31, warp = t >> 5;
    const int last = sel[b * S_ + S_ - 1];
    const float* abrow = ab + ((size_t)b * N_ + last) * N_;

    int u = 0;
    float val = -3.0e38f;
    const bool active = (t < U_);
    if (active) {
        u = unsel[b * U_ + t];
        val = logits[b * L_ + 1 + t] + abrow[u];
    }
    float m = val;
    #pragma unroll
    for (int off = 16; off; off >>= 1) m = fmaxf(m, __shfl_xor_sync(0xffffffffu, m, off));
    if (lane == 0) red[warp] = m;
    __syncthreads();
    if (warp == 0) {
        float mm = red[lane];
        #pragma unroll
        for (int off = 16; off; off >>= 1) mm = fmaxf(mm, __shfl_xor_sync(0xffffffffu, mm, off));
        red[lane] = mm;
    }
    __syncthreads();
    m = red[0];
    __syncthreads();
    const float e = active ? __expf(val - m) : 0.f;
    float s = e;
    #pragma unroll
    for (int off = 16; off; off >>= 1) s += __shfl_xor_sync(0xffffffffu, s, off);
    if (lane == 0) red[warp] = s;
    __syncthreads();
    if (warp == 0) {
        float ss = red[lane];
        #pragma unroll
        for (int off = 16; off; off >>= 1) ss += __shfl_xor_sync(0xffffffffu, ss, off);
        red[lane] = ss;
    }
    __syncthreads();
    const float inv = 1.f / red[0];

    for (int i = t; i < N_; i += 1024) out[(size_t)b * N_ + i] = -2.0f;
    __syncthreads();
    if (active) {
        float p = e * inv;
        if (p <= 1e-5f) p += 1e-7f;
        out[(size_t)b * N_ + u] = p;
    }
}

// ---------------- launch ----------------
extern "C" void kernel_launch(void* const* d_in, const int* in_sizes, int n_in,
                              void* d_out, int out_size) {
    (void)in_sizes; (void)n_in; (void)out_size;
    const float* data   = (const float*)d_in[0];
    const float* ab     = (const float*)d_in[1];
    const float* Wfirst = (const float*)d_in[2];
    const float* bfirst = (const float*)d_in[3];
    const float* Wlast  = (const float*)d_in[4];
    const float* blast  = (const float*)d_in[5];
    const float* Wq     = (const float*)d_in[6];
    const float* Wk     = (const float*)d_in[7];
    const float* Wv     = (const float*)d_in[8];
    const float* Wo     = (const float*)d_in[9];
    const float* bo     = (const float*)d_in[10];
    const float* W1     = (const float*)d_in[11];
    const float* b1     = (const float*)d_in[12];
    const float* W2     = (const float*)d_in[13];
    const float* b2     = (const float*)d_in[14];
    const float* Wfin   = (const float*)d_in[15];
    const float* bfin   = (const float*)d_in[16];
    const int*   sel    = (const int*)d_in[17];
    float* out = (float*)d_out;

    void *px, *plog, *pun, *pxb, *pqb, *pkb, *pvb, *pob, *pwb;
    cudaGetSymbolAddress(&px,   g_x);
    cudaGetSymbolAddress(&plog, g_logits);
    cudaGetSymbolAddress(&pun,  g_unsel);
    cudaGetSymbolAddress(&pxb,  g_xb);
    cudaGetSymbolAddress(&pqb,  g_qb);
    cudaGetSymbolAddress(&pkb,  g_kb);
    cudaGetSymbolAddress(&pvb,  g_vb);
    cudaGetSymbolAddress(&pob,  g_ob);
    cudaGetSymbolAddress(&pwb,  g_wb);
    float* x      = (float*)px;
    float* logits = (float*)plog;
    int*   unsel  = (int*)pun;
    __nv_bfloat16* xb = (__nv_bfloat16*)pxb;
    __nv_bfloat16* qb = (__nv_bfloat16*)pqb;
    __nv_bfloat16* kb = (__nv_bfloat16*)pkb;
    __nv_bfloat16* vb = (__nv_bfloat16*)pvb;
    __nv_bfloat16* obuf = (__nv_bfloat16*)pob;
    __nv_bfloat16* wb = (__nv_bfloat16*)pwb;

    cudaFuncSetAttribute(mlp_k, cudaFuncAttributeMaxDynamicSharedMemorySize, SM_MLP_);
    cudaFuncSetAttribute(attn_bf16, cudaFuncAttributeMaxDynamicSharedMemorySize, SM_ATT_);

    unselect_k<<<B_, 1024>>>(sel, unsel);
    build_cvt_k<<<GATH_BLKS_ + CVT_BLKS_, 1024>>>(
        data, sel, unsel, Wfirst, bfirst, Wlast, blast,
        Wq, Wk, Wv, Wo, W1, W2, wb, x, xb);

    const dim3 gqkv(3, MT_);
    const dim3 gattn(B_ * H_, QTILES_);
    for (int il = 0; il < NL_; il++) {
        const __nv_bfloat16* wqb = wb + (size_t)il * D_ * HK_;
        const __nv_bfloat16* wkb = wb + SQW_ + (size_t)il * D_ * HK_;
        const __nv_bfloat16* wvb = wb + 2 * SQW_ + (size_t)il * D_ * HK_;
        const __nv_bfloat16* wob = wb + 3 * SQW_ + (size_t)il * HK_ * D_;
        const __nv_bfloat16* w1b = wb + 4 * SQW_ + (size_t)il * D_ * FF_;
        const __nv_bfloat16* w2b = wb + 4 * SQW_ + SFW_ + (size_t)il * FF_ * D_;
        const float* bol = bo + (size_t)il * D_;
        const float* b1l = b1 + (size_t)il * FF_;
        const float* b2l = b2 + (size_t)il * D_;
        const bool last = (il == NL_ - 1);

        gemm_qkv<<<gqkv, 256>>>(xb, wqb, wkb, wvb, qb, kb, vb, M_);
        attn_bf16<<<gattn, 256, SM_ATT_>>>(qb, kb, vb, obuf);
        mlp_k<<<MT64_, 256, SM_MLP_>>>(obuf, wob, bol, w1b, b1l, w2b, b2l, x, xb,
                                       last ? Wfin : nullptr, last ? bfin : nullptr,
                                       logits, M_);
    }

    finalize_k<<<B_, 1024>>>(logits, ab, sel, unsel, out);
}

// round 17
// speedup vs baseline: 1.0784x; 1.0784x over previous
#include <cuda_runtime.h>
#include <cuda_bf16.h>

// ---------------- problem constants ----------------
namespace {
constexpr int B_  = 32;
constexpr int N_  = 1000;
constexpr int S_  = 200;
constexpr int D_  = 128;
constexpr int H_  = 8;
constexpr int DK_ = 16;
constexpr int FF_ = 512;
constexpr int NL_ = 3;
constexpr int HK_ = H_ * DK_;          // 128
constexpr int U_  = N_ - S_;           // 800
constexpr int L_  = U_ + 2;            // 802
constexpr int M_  = B_ * L_;           // 25664
constexpr int MT_ = ((M_ + 127) / 128); // 201
constexpr int MT64_ = M_ / 64;          // 401
constexpr int MP_ = MT_ * 128;
constexpr int QT_ = 128;
constexpr int KT_ = 64;
constexpr int QTILES_  = (L_ + QT_ - 1) / QT_;  // 7
constexpr int NKTILES_ = (L_ + KT_ - 1) / KT_;  // 13
constexpr float LOG2E = 1.44269504088896f;
constexpr float QS_ = 0.25f * LOG2E;
constexpr int SQW_ = NL_ * D_ * HK_;   // 49152
constexpr int SFW_ = NL_ * D_ * FF_;   // 196608
constexpr int WB_TOTAL_ = 4 * SQW_ + 2 * SFW_;  // 589824
constexpr int CVT_BLKS_ = (WB_TOTAL_ + 1023) / 1024;  // 576
constexpr int GATH_BLKS_ = B_ * 7;      // 224
// mlp_k smem layout
constexpr int HTILE_B_ = 64 * 136 * 2;
constexpr int WTILE_B_ = 128 * 136 * 2;
constexpr int SM_AF_  = 0;
constexpr int SM_OB1_ = HTILE_B_;
constexpr int SM_WT_  = 2 * HTILE_B_;
constexpr int SM_LOG_ = 2 * HTILE_B_ + 2 * WTILE_B_;
constexpr int SM_MLP_ = SM_LOG_ + 256;        // 104704
}

// ---------------- device scratch ----------------
__device__ float g_x    [MP_ * D_];
__device__ float g_logits[M_];
__device__ int   g_unsel[B_ * U_];
__device__ __nv_bfloat16 g_xb [MP_ * D_];
__device__ __nv_bfloat16 g_qb [M_ * D_];
__device__ __nv_bfloat16 g_kb [M_ * D_];
__device__ __nv_bfloat16 g_vb [M_ * D_];
__device__ __nv_bfloat16 g_ob [MP_ * D_];
__device__ __nv_bfloat16 g_wb [WB_TOTAL_];

// ---------------- helpers ----------------
__device__ __forceinline__ float ex2(float x) {
    float y;
    asm("ex2.approx.f32 %0, %1;" : "=f"(y) : "f"(x));
    return y;
}

__device__ __forceinline__ unsigned pk(float lo, float hi) {
    unsigned r;
    asm("cvt.rn.bf16x2.f32 %0, %1, %2;" : "=r"(r) : "f"(hi), "f"(lo));
    return r;
}

__device__ __forceinline__ void ldsm4(unsigned& r0, unsigned& r1, unsigned& r2, unsigned& r3,
                                      const void* p) {
    unsigned a = (unsigned)__cvta_generic_to_shared(p);
    asm volatile("ldmatrix.sync.aligned.m8n8.x4.shared.b16 {%0,%1,%2,%3}, [%4];"
                 : "=r"(r0), "=r"(r1), "=r"(r2), "=r"(r3) : "r"(a));
}
__device__ __forceinline__ void ldsm4t(unsigned& r0, unsigned& r1, unsigned& r2, unsigned& r3,
                                       const void* p) {
    unsigned a = (unsigned)__cvta_generic_to_shared(p);
    asm volatile("ldmatrix.sync.aligned.m8n8.x4.trans.shared.b16 {%0,%1,%2,%3}, [%4];"
                 : "=r"(r0), "=r"(r1), "=r"(r2), "=r"(r3) : "r"(a));
}

// accumulate in place: D = A*B + D
__device__ __forceinline__ void mma_bf16(float& d0, float& d1, float& d2, float& d3,
                                         unsigned a0, unsigned a1, unsigned a2, unsigned a3,
                                         unsigned b0, unsigned b1) {
    asm volatile(
        "mma.sync.aligned.m16n8k16.row.col.f32.bf16.bf16.f32 "
        "{%0,%1,%2,%3}, {%4,%5,%6,%7}, {%8,%9}, {%0,%1,%2,%3};"
        : "+f"(d0), "+f"(d1), "+f"(d2), "+f"(d3)
        : "r"(a0), "r"(a1), "r"(a2), "r"(a3), "r"(b0), "r"(b1));
}

// zero accumulator: D = A*B + 0 (no per-tile zero-init MOVs)
__device__ __forceinline__ void mma_bf16_z(float& d0, float& d1, float& d2, float& d3,
                                           unsigned a0, unsigned a1, unsigned a2, unsigned a3,
                                           unsigned b0, unsigned b1) {
    asm volatile(
        "mma.sync.aligned.m16n8k16.row.col.f32.bf16.bf16.f32 "
        "{%0,%1,%2,%3}, {%4,%5,%6,%7}, {%8,%9}, {%10,%11,%12,%13};"
        : "=f"(d0), "=f"(d1), "=f"(d2), "=f"(d3)
        : "r"(a0), "r"(a1), "r"(a2), "r"(a3), "r"(b0), "r"(b1),
          "f"(0.f), "f"(0.f), "f"(0.f), "f"(0.f));
}

__device__ __forceinline__ void cp16(void* smem, const void* gmem) {
    unsigned s = (unsigned)__cvta_generic_to_shared(smem);
    asm volatile("cp.async.ca.shared.global [%0], [%1], 16;" :: "r"(s), "l"(gmem));
}
__device__ __forceinline__ void cp_commit() { asm volatile("cp.async.commit_group;"); }
__device__ __forceinline__ void cp_wait0()  { asm volatile("cp.async.wait_group 0;"); }
__device__ __forceinline__ void cp_wait1()  { asm volatile("cp.async.wait_group 1;"); }

// ---------------- 1a) unselected-index compaction ----------------
__global__ void __launch_bounds__(1024) unselect_k(const int* __restrict__ sel,
                                                   int* __restrict__ unsel) {
    __shared__ int keep[1024];
    __shared__ int scan[1024];
    const int b = blockIdx.x, t = threadIdx.x;
    keep[t] = (t < N_) ? 1 : 0;
    __syncthreads();
    if (t < S_) keep[sel[b * S_ + t]] = 0;
    __syncthreads();
    const int k = keep[t];
    scan[t] = k;
    __syncthreads();
    #pragma unroll
    for (int off = 1; off < 1024; off <<= 1) {
        int add = (t >= off) ? scan[t - off] : 0;
        __syncthreads();
        scan[t] += add;
        __syncthreads();
    }
    if (k && t < N_) unsel[b * U_ + scan[t] - 1] = t;
}

// ---------------- 1b) parallel build x0 + weight cvt ----------------
__global__ void __launch_bounds__(1024) build_cvt_k(
    const float* __restrict__ data, const int* __restrict__ sel,
    const int* __restrict__ unsel,
    const float* __restrict__ Wf, const float* __restrict__ bf,
    const float* __restrict__ Wl, const float* __restrict__ bl,
    const float* __restrict__ Wq, const float* __restrict__ Wk,
    const float* __restrict__ Wv, const float* __restrict__ Wo,
    const float* __restrict__ W1, const float* __restrict__ W2,
    __nv_bfloat16* __restrict__ wb,
    float* __restrict__ x, __nv_bfloat16* __restrict__ xb)
{
    const int t = threadIdx.x;
    if (blockIdx.x >= GATH_BLKS_) {
        const int i = (blockIdx.x - GATH_BLKS_) * 1024 + t;
        if (i >= WB_TOTAL_) return;
        float v;
        if      (i <     SQW_)        v = Wq[i];
        else if (i < 2 * SQW_)        v = Wk[i - SQW_];
        else if (i < 3 * SQW_)        v = Wv[i - 2 * SQW_];
        else if (i < 4 * SQW_)        v = Wo[i - 3 * SQW_];
        else if (i < 4 * SQW_ + SFW_) v = W1[i - 4 * SQW_];
        else                          v = W2[i - 4 * SQW_ - SFW_];
        wb[i] = __float2bfloat16(v);
        return;
    }

    const int b = blockIdx.x / 7;
    const int chunk = blockIdx.x % 7;
    const int r0 = chunk * 128;

    #pragma unroll
    for (int it = 0; it < 4; it++) {
        const int idx = t + it * 1024;
        const int row = idx >> 5;
        const int c4 = (idx & 31) * 4;
        const int l = r0 + row;
        if (l >= L_ || l == 0 || l == L_ - 1) continue;
        const int node = unsel[b * U_ + (l - 1)];
        const float4 v = *(const float4*)&data[((size_t)b * N_ + node) * D_ + c4];
        const size_t ro = ((size_t)b * L_ + l) * D_ + c4;
        *(float4*)&x[ro] = v;
        uint2 w; w.x = pk(v.x, v.y); w.y = pk(v.z, v.w);
        *(uint2*)&xb[ro] = w;
    }

    if (chunk == 0 || chunk == 6) {
        __shared__ float vin[128];
        const bool lastr = (chunk == 6);
        const int node = sel[b * S_ + (lastr ? S_ - 1 : 0)];
        if (t < 128) vin[t] = data[((size_t)b * N_ + node) * D_ + t];
        __syncthreads();
        if (t < 128) {
            const float* W  = lastr ? Wl : Wf;
            const float* bb = lastr ? bl : bf;
            float acc = bb[t];
            #pragma unroll 16
            for (int i = 0; i < D_; i++) acc = fmaf(vin[i], W[i * D_ + t], acc);
            const int l = lastr ? (L_ - 1) : 0;
            const size_t ro = ((size_t)b * L_ + l) * D_ + t;
            x[ro] = acc;
            xb[ro] = __float2bfloat16(acc);
        }
    }
}

// ---------------- 2) fused MLP (unchanged) ----------------
__device__ __forceinline__ void phase_compute(
    const __nv_bfloat16 (*__restrict__ Asm)[136],
    const __nv_bfloat16 (*__restrict__ Wtb)[136],
    int arow, int ac8, int kr, int wn, int lane,
    float (&dst)[8][4])
{
    #pragma unroll
    for (int kt = 0; kt < 8; kt++) {
        unsigned aa[4];
        ldsm4(aa[0], aa[1], aa[2], aa[3], &Asm[arow][kt * 16 + ac8]);
        #pragma unroll
        for (int ntp = 0; ntp < 4; ntp++) {
            unsigned b0, b1v, b2v, b3;
            const int nn = wn * 64 + ntp * 16 + ((lane >> 4) & 1) * 8;
            ldsm4t(b0, b1v, b2v, b3, &Wtb[kt * 16 + kr][nn]);
            mma_bf16(dst[2*ntp][0], dst[2*ntp][1], dst[2*ntp][2], dst[2*ntp][3],
                     aa[0], aa[1], aa[2], aa[3], b0, b1v);
            mma_bf16(dst[2*ntp+1][0], dst[2*ntp+1][1], dst[2*ntp+1][2], dst[2*ntp+1][3],
                     aa[0], aa[1], aa[2], aa[3], b2v, b3);
        }
    }
}

__global__ void __launch_bounds__(256, 2) mlp_k(
    const __nv_bfloat16* __restrict__ ob,
    const __nv_bfloat16* __restrict__ Wo, const float* __restrict__ bo,
    const __nv_bfloat16* __restrict__ W1, const float* __restrict__ b1,
    const __nv_bfloat16* __restrict__ W2, const float* __restrict__ b2,
    float* __restrict__ xf, __nv_bfloat16* __restrict__ xb,
    const float* __restrict__ Wfin, const float* __restrict__ bfin,
    float* __restrict__ logits, int Mreal)
{
    extern __shared__ char dyn[];
    __nv_bfloat16 (*Af)[136]      = (__nv_bfloat16(*)[136])(dyn + SM_AF_);
    __nv_bfloat16 (*Ob1)[136]     = (__nv_bfloat16(*)[136])(dyn + SM_OB1_);
    __nv_bfloat16 (*Wt)[128][136] = (__nv_bfloat16(*)[128][136])(dyn + SM_WT_);
    float* slog = (float*)(dyn + SM_LOG_);

    const int bm = blockIdx.x * 64;
    const int tid = threadIdx.x;
    const int warp = tid >> 5, lane = tid & 31;
    const int wm = warp >> 1, wn = warp & 1;
    const int g = lane >> 2, tg = lane & 3;

    auto stage_w = [&](int buf, const __nv_bfloat16* src, int ld, int row0, int col0) {
        #pragma unroll
        for (int i = 0; i < 8; i++) {
            const int idx = tid + i * 256;
            const int r = idx >> 4, c8 = (idx & 15) * 8;
            cp16(&Wt[buf][r][c8], &src[(size_t)(row0 + r) * ld + col0 + c8]);
        }
        cp_commit();
    };

    #pragma unroll
    for (int i = 0; i < 4; i++) {
        const int idx = tid + i * 256;
        cp16(&Af[idx >> 4][(idx & 15) * 8], &ob[(size_t)(bm + (idx >> 4)) * D_ + (idx & 15) * 8]);
    }
    cp_commit();
    stage_w(0, Wo, D_, 0, 0);

    float acc[8][4];
    #pragma unroll
    for (int b = 0; b < 8; b++)
        #pragma unroll
        for (int c = 0; c < 4; c++) acc[b][c] = 0.f;

    const int lr_lo = wm * 16 + g;
    const int lr_hi = lr_lo + 8;
    const int arow = wm * 16 + (lane & 7) + ((lane >> 3) & 1) * 8;
    const int ac8  = ((lane >> 4) & 1) * 8;
    const int kr   = (lane & 7) + ((lane >> 3) & 1) * 8;

    cp_wait0();
    __syncthreads();
    stage_w(1, W1, FF_, 0, 0);
    phase_compute(Af, Wt[0], arow, ac8, kr, wn, lane, acc);
    __syncthreads();
    #pragma unroll
    for (int nt = 0; nt < 8; nt++) {
        const int cn = wn * 64 + nt * 8 + tg * 2;
        const float b0 = bo[cn], b1v = bo[cn + 1];
        const float2 rlo = *(const float2*)&xf[(size_t)(bm + lr_lo) * D_ + cn];
        const float2 rhi = *(const float2*)&xf[(size_t)(bm + lr_hi) * D_ + cn];
        acc[nt][0] += b0 + rlo.x;  acc[nt][1] += b1v + rlo.y;
        acc[nt][2] += b0 + rhi.x;  acc[nt][3] += b1v + rhi.y;
        *(unsigned*)&Ob1[lr_lo][cn] = pk(acc[nt][0], acc[nt][1]);
        *(unsigned*)&Ob1[lr_hi][cn] = pk(acc[nt][2], acc[nt][3]);
    }

    float acch[8][4];
    #pragma unroll 1
    for (int c = 0; c < 4; c++) {
        const int p1 = 1 + 2 * c;
        const int b1f = p1 & 1;
        const int b2f = (p1 + 1) & 1;

        #pragma unroll
        for (int b = 0; b < 8; b++)
            #pragma unroll
            for (int d = 0; d < 4; d++) acch[b][d] = 0.f;

        cp_wait0();
        __syncthreads();
        stage_w(b2f, W2, D_, c * 128, 0);
        phase_compute(Ob1, Wt[b1f], arow, ac8, kr, wn, lane, acch);
        __syncthreads();
        #pragma unroll
        for (int nt = 0; nt < 8; nt++) {
            const int cn = wn * 64 + nt * 8 + tg * 2;
            const float bb0 = b1[c * 128 + cn], bb1 = b1[c * 128 + cn + 1];
            const float v0 = fmaxf(acch[nt][0] + bb0, 0.f);
            const float v1 = fmaxf(acch[nt][1] + bb1, 0.f);
            const float v2 = fmaxf(acch[nt][2] + bb0, 0.f);
            const float v3 = fmaxf(acch[nt][3] + bb1, 0.f);
            *(unsigned*)&Af[lr_lo][cn] = pk(v0, v1);
            *(unsigned*)&Af[lr_hi][cn] = pk(v2, v3);
        }
        cp_wait0();
        __syncthreads();
        if (c + 1 < 4) stage_w(b1f, W1, FF_, 0, (c + 1) * 128);
        phase_compute(Af, Wt[b2f], arow, ac8, kr, wn, lane, acc);
        __syncthreads();
    }

    const bool do_log = (Wfin != nullptr);
    if (do_log && tid < 64) slog[tid] = 0.f;
    if (do_log) __syncthreads();

    float part[2] = {0.f, 0.f};
    #pragma unroll
    for (int nt = 0; nt < 8; nt++) {
        const int cn = wn * 64 + nt * 8 + tg * 2;
        const float b0 = b2[cn], b1v = b2[cn + 1];
        const float v0 = acc[nt][0] + b0, v1 = acc[nt][1] + b1v;
        const float v2 = acc[nt][2] + b0, v3 = acc[nt][3] + b1v;
        *(float2*)&xf[(size_t)(bm + lr_lo) * D_ + cn] = make_float2(v0, v1);
        *(float2*)&xf[(size_t)(bm + lr_hi) * D_ + cn] = make_float2(v2, v3);
        *(unsigned*)&xb[(size_t)(bm + lr_lo) * D_ + cn] = pk(v0, v1);
        *(unsigned*)&xb[(size_t)(bm + lr_hi) * D_ + cn] = pk(v2, v3);
        if (do_log) {
            const float w0 = Wfin[cn], w1 = Wfin[cn + 1];
            part[0] += v0 * w0 + v1 * w1;
            part[1] += v2 * w0 + v3 * w1;
        }
    }
    if (do_log) {
        #pragma unroll
        for (int hh = 0; hh < 2; hh++) {
            part[hh] += __shfl_xor_sync(0xffffffffu, part[hh], 1);
            part[hh] += __shfl_xor_sync(0xffffffffu, part[hh], 2);
        }
        if (tg == 0) {
            atomicAdd(&slog[lr_lo], part[0]);
            atomicAdd(&slog[lr_hi], part[1]);
        }
        __syncthreads();
        if (tid < 64 && bm + tid < Mreal) logits[bm + tid] = slog[tid] + bfin[0];
    }
}

// ---------------- 3) fused QKV GEMM (unchanged) ----------------
struct GemmSmem {
    __nv_bfloat16 As[3][128][24];
    __nv_bfloat16 Bs[3][16][136];
};

__device__ __forceinline__ void gemm_step(
    const GemmSmem& sm, int buf, int wm, int wn, int lane, float acc[2][8][4])
{
    unsigned aa[2][4];
    #pragma unroll
    for (int mt = 0; mt < 2; mt++) {
        const int row = wm * 32 + mt * 16 + (lane & 7) + ((lane >> 3) & 1) * 8;
        const int c8 = ((lane >> 4) & 1) * 8;
        ldsm4(aa[mt][0], aa[mt][1], aa[mt][2], aa[mt][3], &sm.As[buf][row][c8]);
    }
    const int kr = (lane & 7) + ((lane >> 3) & 1) * 8;
    #pragma unroll
    for (int ntp = 0; ntp < 4; ntp++) {
        unsigned b0, b1, b2, b3;
        const int nn = wn * 64 + ntp * 16 + ((lane >> 4) & 1) * 8;
        ldsm4t(b0, b1, b2, b3, &sm.Bs[buf][kr][nn]);
        #pragma unroll
        for (int mt = 0; mt < 2; mt++) {
            mma_bf16(acc[mt][2*ntp][0], acc[mt][2*ntp][1], acc[mt][2*ntp][2], acc[mt][2*ntp][3],
                     aa[mt][0], aa[mt][1], aa[mt][2], aa[mt][3], b0, b1);
            mma_bf16(acc[mt][2*ntp+1][0], acc[mt][2*ntp+1][1], acc[mt][2*ntp+1][2], acc[mt][2*ntp+1][3],
                     aa[mt][0], aa[mt][1], aa[mt][2], aa[mt][3], b2, b3);
        }
    }
}

__global__ void __launch_bounds__(256) gemm_qkv(
    const __nv_bfloat16* __restrict__ A,
    const __nv_bfloat16* __restrict__ Wq, const __nv_bfloat16* __restrict__ Wk,
    const __nv_bfloat16* __restrict__ Wv,
    __nv_bfloat16* __restrict__ Cq, __nv_bfloat16* __restrict__ Ck,
    __nv_bfloat16* __restrict__ Cv, int Mreal)
{
    __shared__ GemmSmem sm;
    const int which = blockIdx.x;
    const __nv_bfloat16* W = (which == 0) ? Wq : (which == 1) ? Wk : Wv;
    __nv_bfloat16* C = (which == 0) ? Cq : (which == 1) ? Ck : Cv;
    const float osc = (which == 0) ? QS_ : 1.f;
    const int bm = blockIdx.y * 128;
    const int tid = threadIdx.x;
    const int warp = tid >> 5, lane = tid & 31;
    const int wm = warp >> 1, wn = warp & 1;
    const int g = lane >> 2, tg = lane & 3;

    const int arow = tid >> 1, ahalf = (tid & 1) * 8;
    const int brow = tid >> 4, bcol = (tid & 15) * 8;

    float acc[2][8][4];
    #pragma unroll
    for (int a = 0; a < 2; a++)
        #pragma unroll
        for (int b = 0; b < 8; b++)
            #pragma unroll
            for (int c = 0; c < 4; c++) acc[a][b][c] = 0.f;

    cp16(&sm.As[0][arow][ahalf], &A[(size_t)(bm + arow) * D_ + ahalf]);
    cp16(&sm.Bs[0][brow][bcol], &W[(size_t)brow * HK_ + bcol]);
    cp_commit();
    cp16(&sm.As[1][arow][ahalf], &A[(size_t)(bm + arow) * D_ + 16 + ahalf]);
    cp16(&sm.Bs[1][brow][bcol], &W[(size_t)(16 + brow) * HK_ + bcol]);
    cp_commit();

    int buf = 0;
    #pragma unroll 1
    for (int kt = 0; kt < 8; kt++) {
        if (kt + 1 < 8) cp_wait1(); else cp_wait0();
        __syncthreads();
        if (kt + 2 < 8) {
            const int k0 = (kt + 2) * 16;
            const int nb = (buf + 2 >= 3) ? buf - 1 : buf + 2;
            cp16(&sm.As[nb][arow][ahalf], &A[(size_t)(bm + arow) * D_ + k0 + ahalf]);
            cp16(&sm.Bs[nb][brow][bcol], &W[(size_t)(k0 + brow) * HK_ + bcol]);
            cp_commit();
        }
        gemm_step(sm, buf, wm, wn, lane, acc);
        buf = (buf + 1 == 3) ? 0 : buf + 1;
    }

    #pragma unroll
    for (int mt = 0; mt < 2; mt++) {
        const int r_lo = bm + wm * 32 + mt * 16 + g;
        const int r_hi = r_lo + 8;
        #pragma unroll
        for (int nt = 0; nt < 8; nt++) {
            const int cn = wn * 64 + nt * 8 + tg * 2;
            const int hh = cn >> 4, dk = cn & 15;
            if (r_lo < Mreal) {
                const int bb = r_lo / L_, ll = r_lo - bb * L_;
                *(unsigned*)&C[(((size_t)bb * H_ + hh) * L_ + ll) * DK_ + dk] =
                    pk(acc[mt][nt][0] * osc, acc[mt][nt][1] * osc);
            }
            if (r_hi < Mreal) {
                const int bb = r_hi / L_, ll = r_hi - bb * L_;
                *(unsigned*)&C[(((size_t)bb * H_ + hh) * L_ + ll) * DK_ + dk] =
                    pk(acc[mt][nt][2] * osc, acc[mt][nt][3] * osc);
            }
        }
    }
}

// ---------------- 4) bf16 flash attention, KT=64 (R15) + zero-accum QK mma ----------------
__global__ void __launch_bounds__(256) attn_bf16(
    const __nv_bfloat16* __restrict__ q, const __nv_bfloat16* __restrict__ k,
    const __nv_bfloat16* __restrict__ v, __nv_bfloat16* __restrict__ o)
{
    __shared__ __align__(16) __nv_bfloat16 Ks[2][KT_][24];
    __shared__ __align__(16) __nv_bfloat16 Vs[2][KT_][24];
    __shared__ __align__(16) unsigned Pp[8][16][36];

    const int bh = blockIdx.x;
    const int b = bh >> 3, h = bh & 7;
    const int qt = blockIdx.y;
    const int tid = threadIdx.x, lane = tid & 31, warp = tid >> 5;
    const int g = lane >> 2, tg = lane & 3;

    const __nv_bfloat16* qp = q + (size_t)bh * L_ * DK_;
    const __nv_bfloat16* kp = k + (size_t)bh * L_ * DK_;
    const __nv_bfloat16* vp = v + (size_t)bh * L_ * DK_;

    const int r0 = qt * QT_ + warp * 16 + g;
    const int r1 = r0 + 8;
    const int r0c = r0 < L_ ? r0 : L_ - 1;
    const int r1c = r1 < L_ ? r1 : L_ - 1;
    const unsigned qa0 = *(const unsigned*)&qp[(size_t)r0c * DK_ + 2 * tg];
    const unsigned qa1 = *(const unsigned*)&qp[(size_t)r1c * DK_ + 2 * tg];
    const unsigned qa2 = *(const unsigned*)&qp[(size_t)r0c * DK_ + 2 * tg + 8];
    const unsigned qa3 = *(const unsigned*)&qp[(size_t)r1c * DK_ + 2 * tg + 8];

    float m0 = -1e30f, m1 = -1e30f, l0 = 0.f, l1 = 0.f;
    float oc[2][4];
    #pragma unroll
    for (int nt = 0; nt < 2; nt++)
        #pragma unroll
        for (int c = 0; c < 4; c++) oc[nt][c] = 0.f;

    const int srow = (tid & 127) >> 1;
    const int shalf = (tid & 1) * 8;
    const bool isv = tid >= 128;

    auto stage = [&](int buf, int j0) {
        int jc = j0 + srow; if (jc > L_ - 1) jc = L_ - 1;
        const __nv_bfloat16* src = (isv ? vp : kp) + (size_t)jc * DK_ + shalf;
        if (isv) cp16(&Vs[buf][srow][shalf], src);
        else     cp16(&Ks[buf][srow][shalf], src);
    };

    stage(0, 0);
    cp_commit();

    #pragma unroll 1
    for (int ti = 0; ti < NKTILES_; ti++) {
        const int buf = ti & 1;
        const int j0 = ti * KT_;
        cp_wait0();
        __syncthreads();
        if (ti + 1 < NKTILES_) { stage(buf ^ 1, j0 + KT_); cp_commit(); }

        // S = Q·K^T, single k-step per element -> zero-accumulator mma (no init MOVs)
        float sc[8][4];
        #pragma unroll
        for (int ntp = 0; ntp < 4; ntp++) {
            unsigned b0, b1, b2, b3;
            const int jrow = ntp * 16 + (lane & 7) + ((lane >> 4) & 1) * 8;
            const int kcol = ((lane >> 3) & 1) * 8;
            ldsm4(b0, b1, b2, b3, &Ks[buf][jrow][kcol]);
            mma_bf16_z(sc[2*ntp][0], sc[2*ntp][1], sc[2*ntp][2], sc[2*ntp][3],
                       qa0, qa1, qa2, qa3, b0, b1);
            mma_bf16_z(sc[2*ntp+1][0], sc[2*ntp+1][1], sc[2*ntp+1][2], sc[2*ntp+1][3],
                       qa0, qa1, qa2, qa3, b2, b3);
        }
        if (j0 + KT_ > L_) {
            #pragma unroll
            for (int nt = 0; nt < 8; nt++) {
                const int c = j0 + nt * 8 + 2 * tg;
                if (c     >= L_) { sc[nt][0] = -1e30f; sc[nt][2] = -1e30f; }
                if (c + 1 >= L_) { sc[nt][1] = -1e30f; sc[nt][3] = -1e30f; }
            }
        }
        float nm0 = m0, nm1 = m1;
        #pragma unroll
        for (int nt = 0; nt < 8; nt++) {
            nm0 = fmaxf(nm0, fmaxf(sc[nt][0], sc[nt][1]));
            nm1 = fmaxf(nm1, fmaxf(sc[nt][2], sc[nt][3]));
        }
        nm0 = fmaxf(nm0, __shfl_xor_sync(0xffffffffu, nm0, 1));
        nm0 = fmaxf(nm0, __shfl_xor_sync(0xffffffffu, nm0, 2));
        nm1 = fmaxf(nm1, __shfl_xor_sync(0xffffffffu, nm1, 1));
        nm1 = fmaxf(nm1, __shfl_xor_sync(0xffffffffu, nm1, 2));
        const float f0 = ex2(m0 - nm0);
        const float f1 = ex2(m1 - nm1);
        m0 = nm0; m1 = nm1;
        l0 *= f0; l1 *= f1;
        #pragma unroll
        for (int nt = 0; nt < 2; nt++) {
            oc[nt][0] *= f0; oc[nt][1] *= f0;
            oc[nt][2] *= f1; oc[nt][3] *= f1;
        }
        float rs0 = 0.f, rs1 = 0.f;
        #pragma unroll
        for (int nt = 0; nt < 8; nt++) {
            const float p0 = ex2(sc[nt][0] - m0);
            const float p1 = ex2(sc[nt][1] - m0);
            const float p2 = ex2(sc[nt][2] - m1);
            const float p3 = ex2(sc[nt][3] - m1);
            rs0 += p0 + p1;
            rs1 += p2 + p3;
            Pp[warp][g    ][nt * 4 + tg] = pk(p0, p1);
            Pp[warp][g + 8][nt * 4 + tg] = pk(p2, p3);
        }
        rs0 += __shfl_xor_sync(0xffffffffu, rs0, 1);
        rs0 += __shfl_xor_sync(0xffffffffu, rs0, 2);
        rs1 += __shfl_xor_sync(0xffffffffu, rs1, 1);
        rs1 += __shfl_xor_sync(0xffffffffu, rs1, 2);
        l0 += rs0; l1 += rs1;
        __syncwarp();
        #pragma unroll
        for (int ks = 0; ks < 4; ks++) {
            unsigned a0, a1, a2, a3;
            const unsigned* pa = &Pp[warp][(lane & 7) + ((lane >> 3) & 1) * 8]
                                         [ks * 8 + ((lane >> 4) & 1) * 4];
            ldsm4(a0, a1, a2, a3, pa);
            unsigned v0, v1, v2, v3;
            const int jrow = ks * 16 + (lane & 7) + ((lane >> 3) & 1) * 8;
            const int dkc = ((lane >> 4) & 1) * 8;
            ldsm4t(v0, v1, v2, v3, &Vs[buf][jrow][dkc]);
            mma_bf16(oc[0][0], oc[0][1], oc[0][2], oc[0][3], a0, a1, a2, a3, v0, v1);
            mma_bf16(oc[1][0], oc[1][1], oc[1][2], oc[1][3], a0, a1, a2, a3, v2, v3);
        }
        __syncwarp();
    }

    const float inv0 = 1.f / l0;
    const float inv1 = 1.f / l1;
    #pragma unroll
    for (int nt = 0; nt < 2; nt++) {
        const int dn = h * DK_ + nt * 8 + 2 * tg;
        if (r0 < L_)
            *(unsigned*)&o[((size_t)b * L_ + r0) * HK_ + dn] =
                pk(oc[nt][0] * inv0, oc[nt][1] * inv0);
        if (r1 < L_)
            *(unsigned*)&o[((size_t)b * L_ + r1) * HK_ + dn] =
                pk(oc[nt][2] * inv1, oc[nt][3] * inv1);
    }
}

// ---------------- 5) finalize (unchanged) ----------------
__global__ void __launch_bounds__(1024) finalize_k(
    const float* __restrict__ logits, const float* __restrict__ ab,
    const int* __restrict__ sel, const int* __restrict__ unsel,
    float* __restrict__ out)
{
    __shared__ float red[32];
    const int b = blockIdx.x, t = threadIdx.x;
    const int lane = t & 31, warp = t >> 5;
    const int last = sel[b * S_ + S_ - 1];
    const float* abrow = ab + ((size_t)b * N_ + last) * N_;

    int u = 0;
    float val = -3.0e38f;
    const bool active = (t < U_);
    if (active) {
        u = unsel[b * U_ + t];
        val = logits[b * L_ + 1 + t] + abrow[u];
    }
    float m = val;
    #pragma unroll
    for (int off = 16; off; off >>= 1) m = fmaxf(m, __shfl_xor_sync(0xffffffffu, m, off));
    if (lane == 0) red[warp] = m;
    __syncthreads();
    if (warp == 0) {
        float mm = red[lane];
        #pragma unroll
        for (int off = 16; off; off >>= 1) mm = fmaxf(mm, __shfl_xor_sync(0xffffffffu, mm, off));
        red[lane] = mm;
    }
    __syncthreads();
    m = red[0];
    __syncthreads();
    const float e = active ? __expf(val - m) : 0.f;
    float s = e;
    #pragma unroll
    for (int off = 16; off; off >>= 1) s += __shfl_xor_sync(0xffffffffu, s, off);
    if (lane == 0) red[warp] = s;
    __syncthreads();
    if (warp == 0) {
        float ss = red[lane];
        #pragma unroll
        for (int off = 16; off; off >>= 1) ss += __shfl_xor_sync(0xffffffffu, ss, off);
        red[lane] = ss;
    }
    __syncthreads();
    const float inv = 1.f / red[0];

    for (int i = t; i < N_; i += 1024) out[(size_t)b * N_ + i] = -2.0f;
    __syncthreads();
    if (active) {
        float p = e * inv;
        if (p <= 1e-5f) p += 1e-7f;
        out[(size_t)b * N_ + u] = p;
    }
}

// ---------------- launch ----------------
extern "C" void kernel_launch(void* const* d_in, const int* in_sizes, int n_in,
                              void* d_out, int out_size) {
    (void)in_sizes; (void)n_in; (void)out_size;
    const float* data   = (const float*)d_in[0];
    const float* ab     = (const float*)d_in[1];
    const float* Wfirst = (const float*)d_in[2];
    const float* bfirst = (const float*)d_in[3];
    const float* Wlast  = (const float*)d_in[4];
    const float* blast  = (const float*)d_in[5];
    const float* Wq     = (const float*)d_in[6];
    const float* Wk     = (const float*)d_in[7];
    const float* Wv     = (const float*)d_in[8];
    const float* Wo     = (const float*)d_in[9];
    const float* bo     = (const float*)d_in[10];
    const float* W1     = (const float*)d_in[11];
    const float* b1     = (const float*)d_in[12];
    const float* W2     = (const float*)d_in[13];
    const float* b2     = (const float*)d_in[14];
    const float* Wfin   = (const float*)d_in[15];
    const float* bfin   = (const float*)d_in[16];
    const int*   sel    = (const int*)d_in[17];
    float* out = (float*)d_out;

    void *px, *plog, *pun, *pxb, *pqb, *pkb, *pvb, *pob, *pwb;
    cudaGetSymbolAddress(&px,   g_x);
    cudaGetSymbolAddress(&plog, g_logits);
    cudaGetSymbolAddress(&pun,  g_unsel);
    cudaGetSymbolAddress(&pxb,  g_xb);
    cudaGetSymbolAddress(&pqb,  g_qb);
    cudaGetSymbolAddress(&pkb,  g_kb);
    cudaGetSymbolAddress(&pvb,  g_vb);
    cudaGetSymbolAddress(&pob,  g_ob);
    cudaGetSymbolAddress(&pwb,  g_wb);
    float* x      = (float*)px;
    float* logits = (float*)plog;
    int*   unsel  = (int*)pun;
    __nv_bfloat16* xb = (__nv_bfloat16*)pxb;
    __nv_bfloat16* qb = (__nv_bfloat16*)pqb;
    __nv_bfloat16* kb = (__nv_bfloat16*)pkb;
    __nv_bfloat16* vb = (__nv_bfloat16*)pvb;
    __nv_bfloat16* obuf = (__nv_bfloat16*)pob;
    __nv_bfloat16* wb = (__nv_bfloat16*)pwb;

    cudaFuncSetAttribute(mlp_k, cudaFuncAttributeMaxDynamicSharedMemorySize, SM_MLP_);

    unselect_k<<<B_, 1024>>>(sel, unsel);
    build_cvt_k<<<GATH_BLKS_ + CVT_BLKS_, 1024>>>(
        data, sel, unsel, Wfirst, bfirst, Wlast, blast,
        Wq, Wk, Wv, Wo, W1, W2, wb, x, xb);

    const dim3 gqkv(3, MT_);
    const dim3 gattn(B_ * H_, QTILES_);
    for (int il = 0; il < NL_; il++) {
        const __nv_bfloat16* wqb = wb + (size_t)il * D_ * HK_;
        const __nv_bfloat16* wkb = wb + SQW_ + (size_t)il * D_ * HK_;
        const __nv_bfloat16* wvb = wb + 2 * SQW_ + (size_t)il * D_ * HK_;
        const __nv_bfloat16* wob = wb + 3 * SQW_ + (size_t)il * HK_ * D_;
        const __nv_bfloat16* w1b = wb + 4 * SQW_ + (size_t)il * D_ * FF_;
        const __nv_bfloat16* w2b = wb + 4 * SQW_ + SFW_ + (size_t)il * FF_ * D_;
        const float* bol = bo + (size_t)il * D_;
        const float* b1l = b1 + (size_t)il * FF_;
        const float* b2l = b2 + (size_t)il * D_;
        const bool last = (il == NL_ - 1);

        gemm_qkv<<<gqkv, 256>>>(xb, wqb, wkb, wvb, qb, kb, vb, M_);
        attn_bf16<<<gattn, 256>>>(qb, kb, vb, obuf);
        mlp_k<<<MT64_, 256, SM_MLP_>>>(obuf, wob, bol, w1b, b1l, w2b, b2l, x, xb,
                                       last ? Wfin : nullptr, last ? bfin : nullptr,
                                       logits, M_);
    }

    finalize_k<<<B_, 1024>>>(logits, ab, sel, unsel, out);
}